// round 3
// baseline (speedup 1.0000x reference)
#include <cuda_runtime.h>

// MatrixReconstructionLayer: X[B,8]=[f1,f2,rx,ry,rz,tx,ty,tz] -> F[B,9] (3x3 row-major).
// F = K2inv @ T @ R @ K1inv, closed-form.
// R3: MUFU sin/cos + approx divide (rel err ~1e-6, budget 1e-3), 2 rows/thread
// for MLP+ILP, smem-staged float4 stores.

#define EPSF 1e-8f
#define TPB 256
#define RPB (TPB * 2)          // rows per block = 512

__device__ __forceinline__ void compute_row(const float4 a, const float4 b,
                                            float* __restrict__ sr) {
    const float f1 = a.x, f2 = a.y, rx = a.z, ry = a.w;
    const float rz = b.x, tx = b.y, ty = b.z, tz = b.w;

    // MUFU-based: inputs ~N(0,1), well inside the fast-path accuracy range.
    const float sx = __sinf(rx), cx = __cosf(rx);
    const float sy = __sinf(ry), cy = __cosf(ry);
    const float sz = __sinf(rz), cz = __cosf(rz);

    const float k1 = -__fdividef(1.0f, f1 + EPSF);
    const float k2 = -__fdividef(1.0f, f2 + EPSF);

    // R = Rx @ (Ry @ Rz)
    const float sxsy = sx * sy;
    const float cxsy = cx * sy;

    const float r00 = cy * cz;
    const float r01 = -cy * sz;
    const float r02 = -sy;
    const float r10 = cx * sz - sxsy * cz;
    const float r11 = cx * cz + sxsy * sz;
    const float r12 = -sx * cy;
    const float r20 = sx * sz + cxsy * cz;
    const float r21 = sx * cz - cxsy * sz;
    const float r22 = cx * cy;

    // M = skew(t) @ R
    const float m00 = ty * r20 - tz * r10;
    const float m01 = ty * r21 - tz * r11;
    const float m02 = ty * r22 - tz * r12;
    const float m10 = tz * r00 - tx * r20;
    const float m11 = tz * r01 - tx * r21;
    const float m12 = tz * r02 - tx * r22;
    const float m20 = tx * r10 - ty * r00;
    const float m21 = tx * r11 - ty * r01;
    const float m22 = tx * r12 - ty * r02;

    // F = diag(k2,k2,1) @ M @ diag(k1,k1,1)
    const float k21 = k2 * k1;
    sr[0] = k21 * m00;
    sr[1] = k21 * m01;
    sr[2] = k2 * m02;
    sr[3] = k21 * m10;
    sr[4] = k21 * m11;
    sr[5] = k2 * m12;
    sr[6] = m20 * k1;
    sr[7] = m21 * k1;
    sr[8] = m22;
}

// Fast path: B % RPB == 0. Two rows per thread: 4 LDG.128 in flight, two
// independent compute chains, then a vectorized block copy (4.5 STG.128/thread).
__global__ __launch_bounds__(TPB)
void fmat_kernel_fast(const float* __restrict__ X, float* __restrict__ out) {
    __shared__ __align__(16) float s[RPB * 9];

    const int tid = threadIdx.x;
    const unsigned r0 = blockIdx.x * RPB + tid;          // rows r0 and r0+TPB
    const float4* Xv = reinterpret_cast<const float4*>(X);

    // Issue all 4 loads before any compute.
    const float4 a0 = __ldcs(&Xv[r0 * 2 + 0]);
    const float4 b0 = __ldcs(&Xv[r0 * 2 + 1]);
    const float4 a1 = __ldcs(&Xv[(r0 + TPB) * 2 + 0]);
    const float4 b1 = __ldcs(&Xv[(r0 + TPB) * 2 + 1]);

    compute_row(a0, b0, &s[tid * 9]);                // stride 9: conflict-free
    compute_row(a1, b1, &s[(tid + TPB) * 9]);

    __syncthreads();

    // Block output: RPB*9 = 4608 floats = 1152 float4 = 4.5 per thread.
    const float4* s4 = reinterpret_cast<const float4*>(s);
    float4* out4 = reinterpret_cast<float4*>(out) + (unsigned)blockIdx.x * 1152u;
#pragma unroll
    for (int k = 0; k < 4; k++)
        __stcs(&out4[k * TPB + tid], s4[k * TPB + tid]);
    if (tid < 128)
        __stcs(&out4[4 * TPB + tid], s4[4 * TPB + tid]);
}

// Generic fallback (any B): scalar coalesced stores via smem, precise math kept
// simple; correctness path only.
__global__ __launch_bounds__(TPB)
void fmat_kernel_gen(const float* __restrict__ X, float* __restrict__ out, int B) {
    __shared__ float s[TPB * 9];
    const int tid = threadIdx.x;
    const long long row = (long long)blockIdx.x * TPB + tid;

    if (row < B) {
        const float4* Xv = reinterpret_cast<const float4*>(X);
        float4 a = Xv[row * 2 + 0];
        float4 b = Xv[row * 2 + 1];
        compute_row(a, b, &s[tid * 9]);
    }
    __syncthreads();

    const long long base = (long long)blockIdx.x * (TPB * 9);
    const long long total = (long long)B * 9;
#pragma unroll
    for (int k = 0; k < 9; k++) {
        long long idx = base + k * TPB + tid;
        if (idx < total) out[idx] = s[k * TPB + tid];
    }
}

extern "C" void kernel_launch(void* const* d_in, const int* in_sizes, int n_in,
                              void* d_out, int out_size) {
    const float* X = (const float*)d_in[0];
    float* out = (float*)d_out;
    const int B = in_sizes[0] / 8;
    if (B % RPB == 0) {
        fmat_kernel_fast<<<B / RPB, TPB>>>(X, out);
    } else {
        fmat_kernel_gen<<<(B + TPB - 1) / TPB, TPB>>>(X, out, B);
    }
}